// round 6
// baseline (speedup 1.0000x reference)
#include <cuda_runtime.h>

#define DIM   48
#define NBINS 38

#define BIN_LO   3.25f
#define BIN_STEP (17.5f / 37.0f)    // linspace(3.25, 20.75, 38) spacing
#define BIN_INV  (37.0f / 17.5f)

__device__ __forceinline__ int bin_of(float d) {
    int k = (int)rintf((d - BIN_LO) * BIN_INV);
    k = k < 0 ? 0 : (k > NBINS - 1 ? NBINS - 1 : k);
    float best = fabsf(d - fmaf((float)k, BIN_STEP, BIN_LO));
    if (k > 0) {
        float c = fabsf(d - fmaf((float)(k - 1), BIN_STEP, BIN_LO));
        if (c < best) { best = c; k = k - 1; }
    }
    if (k < NBINS - 1) {
        float c = fabsf(d - fmaf((float)(k + 1), BIN_STEP, BIN_LO));
        if (c < best) { k = k + 1; }
    }
    return k;
}

// 4 lanes per row (48B/thread), 2-step butterfly row stats. W+b folded into
// shared memory once per block (coalesced stage) so the per-row W gather is an
// LDS instead of scattered L1 global wavefronts. 512 threads = 128 rows/block.
// Pair rows and single-LN rows fused into one grid (single rows = tail blocks).
__global__ __launch_bounds__(512, 3) void fused_kernel(
    const float*  __restrict__ x,
    const float4* __restrict__ pair4,
    const float4* __restrict__ single4,
    const float4* __restrict__ W4,
    const float4* __restrict__ b4,
    const float4* __restrict__ gp4,
    const float4* __restrict__ bp4,
    const float4* __restrict__ gm4,
    const float4* __restrict__ bm4,
    float4*       __restrict__ pair_out4,
    float4*       __restrict__ single_out4,
    int L, int total, int blocksP, int lshift)
{
    __shared__ float4 sWb[NBINS * 12];     // W row + bias, folded (7296 B)

    const bool is_pair = (blockIdx.x < blocksP);

    // --- stage W+b coalesced (only needed by pair blocks, but cheap) ---
    if (is_pair) {
        for (int idx = threadIdx.x; idx < NBINS * 12; idx += 512) {
            float4 w = W4[idx];
            float4 c = b4[idx % 12];
            w.x += c.x; w.y += c.y; w.z += c.z; w.w += c.w;
            sWb[idx] = w;
        }
        __syncthreads();
    }

    const float4* src;
    float4*       dst;
    const float4* g4;
    const float4* be4;
    int row, limit;
    {
        int gtid;
        if (is_pair) {
            gtid  = blockIdx.x * 512 + threadIdx.x;
            limit = total;
            src = pair4;   dst = pair_out4;   g4 = gp4; be4 = bp4;
        } else {
            gtid  = (blockIdx.x - blocksP) * 512 + threadIdx.x;
            limit = L;
            src = single4; dst = single_out4; g4 = gm4; be4 = bm4;
        }
        row = gtid >> 2;
        if (row >= limit) return;
    }
    const int lane4 = threadIdx.x & 3;

    // --- load 12 elements of this row (lane-strided float4) ---
    const float4* p = src + (size_t)row * 12 + lane4;
    const float4 v0 = p[0];
    const float4 v1 = p[4];
    const float4 v2 = p[8];

    // --- row stats via 4-lane butterfly ---
    float sum = v0.x + v0.y + v0.z + v0.w
              + v1.x + v1.y + v1.z + v1.w
              + v2.x + v2.y + v2.z + v2.w;
    float ssq = v0.x*v0.x + v0.y*v0.y + v0.z*v0.z + v0.w*v0.w
              + v1.x*v1.x + v1.y*v1.y + v1.z*v1.z + v1.w*v1.w
              + v2.x*v2.x + v2.y*v2.y + v2.z*v2.z + v2.w*v2.w;
    sum += __shfl_xor_sync(0xffffffffu, sum, 1);
    ssq += __shfl_xor_sync(0xffffffffu, ssq, 1);
    sum += __shfl_xor_sync(0xffffffffu, sum, 2);
    ssq += __shfl_xor_sync(0xffffffffu, ssq, 2);

    const float mu  = sum * (1.0f / DIM);
    const float var = ssq * (1.0f / DIM) - mu * mu;
    const float rs  = rsqrtf(var + 1e-5f);

    float4* q = dst + (size_t)row * 12 + lane4;

    if (is_pair) {
        int i, j;
        if (lshift >= 0) { i = row >> lshift; j = row & (L - 1); }
        else             { i = row / L;       j = row - i * L;   }
        const float dx = x[3 * i]     - x[3 * j];
        const float dy = x[3 * i + 1] - x[3 * j + 1];
        const float dz = x[3 * i + 2] - x[3 * j + 2];
        const float d  = sqrtf(dx * dx + dy * dy + dz * dz + 1e-12f);
        const int kbin = bin_of(d);
        const float4* wr = sWb + kbin * 12 + lane4;

        #pragma unroll
        for (int c = 0; c < 3; c++) {
            const float4 v = (c == 0) ? v0 : (c == 1) ? v1 : v2;
            const float4 G = g4 [lane4 + 4 * c];
            const float4 B = be4[lane4 + 4 * c];
            const float4 w = wr[4 * c];
            float4 o;
            o.x = fmaf((v.x - mu) * rs, G.x, B.x + w.x);
            o.y = fmaf((v.y - mu) * rs, G.y, B.y + w.y);
            o.z = fmaf((v.z - mu) * rs, G.z, B.z + w.z);
            o.w = fmaf((v.w - mu) * rs, G.w, B.w + w.w);
            q[4 * c] = o;
        }
    } else {
        #pragma unroll
        for (int c = 0; c < 3; c++) {
            const float4 v = (c == 0) ? v0 : (c == 1) ? v1 : v2;
            const float4 G = g4 [lane4 + 4 * c];
            const float4 B = be4[lane4 + 4 * c];
            float4 o;
            o.x = fmaf((v.x - mu) * rs, G.x, B.x);
            o.y = fmaf((v.y - mu) * rs, G.y, B.y);
            o.z = fmaf((v.z - mu) * rs, G.z, B.z);
            o.w = fmaf((v.w - mu) * rs, G.w, B.w);
            q[4 * c] = o;
        }
    }
}

// ---------------------------------------------------------------------------
extern "C" void kernel_launch(void* const* d_in, const int* in_sizes, int n_in,
                              void* d_out, int out_size) {
    const float* x      = (const float*)d_in[0];
    const float* single = (const float*)d_in[1];
    const float* pair   = (const float*)d_in[2];
    const float* W      = (const float*)d_in[3];
    const float* b      = (const float*)d_in[4];
    const float* gp     = (const float*)d_in[5];
    const float* bp     = (const float*)d_in[6];
    const float* gm     = (const float*)d_in[7];
    const float* bm     = (const float*)d_in[8];

    const int L = in_sizes[1] / DIM;            // single is [1, L, DIM]
    const int total = L * L;

    float* out        = (float*)d_out;
    float* single_out = out;                     // (single_out, pair_out) concatenated
    float* pair_out   = out + (size_t)L * DIM;

    // power-of-two shortcut for row -> (i, j)
    int lshift = -1;
    if ((L & (L - 1)) == 0) {
        lshift = 0;
        while ((1 << lshift) < L) lshift++;
    }

    // 128 rows per block (512 threads, 4 per row)
    const int blocksP = (total + 127) / 128;
    const int blocksS = (L + 127) / 128;

    fused_kernel<<<blocksP + blocksS, 512>>>(
        x,
        (const float4*)pair, (const float4*)single,
        (const float4*)W, (const float4*)b,
        (const float4*)gp, (const float4*)bp,
        (const float4*)gm, (const float4*)bm,
        (float4*)pair_out, (float4*)single_out,
        L, total, blocksP, lshift);
}

// round 7
// speedup vs baseline: 1.0292x; 1.0292x over previous
#include <cuda_runtime.h>

#define DIM   48
#define NBINS 38

#define BIN_LO   3.25f
#define BIN_STEP (17.5f / 37.0f)    // linspace(3.25, 20.75, 38) spacing
#define BIN_INV  (37.0f / 17.5f)

__device__ __forceinline__ int bin_of(float d) {
    int k = (int)rintf((d - BIN_LO) * BIN_INV);
    k = k < 0 ? 0 : (k > NBINS - 1 ? NBINS - 1 : k);
    float best = fabsf(d - fmaf((float)k, BIN_STEP, BIN_LO));
    if (k > 0) {
        float c = fabsf(d - fmaf((float)(k - 1), BIN_STEP, BIN_LO));
        if (c < best) { best = c; k = k - 1; }
    }
    if (k < NBINS - 1) {
        float c = fabsf(d - fmaf((float)(k + 1), BIN_STEP, BIN_LO));
        if (c < best) { k = k + 1; }
    }
    return k;
}

__device__ __forceinline__ void row_stats(const float4& a, const float4& b,
                                          const float4& c, float& mu, float& rs) {
    float sum = a.x + a.y + a.z + a.w
              + b.x + b.y + b.z + b.w
              + c.x + c.y + c.z + c.w;
    float ssq = a.x*a.x + a.y*a.y + a.z*a.z + a.w*a.w
              + b.x*b.x + b.y*b.y + b.z*b.z + b.w*b.w
              + c.x*c.x + c.y*c.y + c.z*c.z + c.w*c.w;
    sum += __shfl_xor_sync(0xffffffffu, sum, 1);
    ssq += __shfl_xor_sync(0xffffffffu, ssq, 1);
    sum += __shfl_xor_sync(0xffffffffu, sum, 2);
    ssq += __shfl_xor_sync(0xffffffffu, ssq, 2);
    mu = sum * (1.0f / DIM);
    const float var = ssq * (1.0f / DIM) - mu * mu;
    rs = rsqrtf(var + 1e-5f);
}

// 4 lanes per row; each thread owns TWO rows (r0 and r0+64) so 6 LDG.128 are in
// flight before any dependent work (MLP=6). W+b folded into shared memory once
// per block. 256 threads = 128 rows/block. Pair rows and single-LN rows fused
// into one grid (single rows = tail blocks).
__global__ __launch_bounds__(256, 4) void fused_kernel(
    const float*  __restrict__ x,
    const float4* __restrict__ pair4,
    const float4* __restrict__ single4,
    const float4* __restrict__ W4,
    const float4* __restrict__ b4,
    const float4* __restrict__ gp4,
    const float4* __restrict__ bp4,
    const float4* __restrict__ gm4,
    const float4* __restrict__ bm4,
    float4*       __restrict__ pair_out4,
    float4*       __restrict__ single_out4,
    int L, int total, int blocksP, int lshift)
{
    __shared__ float4 sWb[NBINS * 12];     // W row + bias, folded (7296 B)

    const bool is_pair = (blockIdx.x < blocksP);

    if (is_pair) {
        for (int idx = threadIdx.x; idx < NBINS * 12; idx += 256) {
            float4 w = W4[idx];
            float4 c = b4[idx % 12];
            w.x += c.x; w.y += c.y; w.z += c.z; w.w += c.w;
            sWb[idx] = w;
        }
        __syncthreads();
    }

    const float4* src;
    float4*       dst;
    const float4* g4;
    const float4* be4;
    int r0, limit;
    if (is_pair) {
        r0    = blockIdx.x * 128 + (threadIdx.x >> 2);
        limit = total;
        src = pair4;   dst = pair_out4;   g4 = gp4; be4 = bp4;
    } else {
        r0    = (blockIdx.x - blocksP) * 128 + (threadIdx.x >> 2);
        limit = L;
        src = single4; dst = single_out4; g4 = gm4; be4 = bm4;
    }
    const int r1 = r0 + 64;
    const bool live0 = (r0 < limit);
    const bool live1 = (r1 < limit);
    if (!live0) return;

    const int lane4 = threadIdx.x & 3;

    // --- issue all 6 loads up front (MLP=6) ---
    const float4* p0 = src + (size_t)r0 * 12 + lane4;
    const float4* p1 = src + (size_t)r1 * 12 + lane4;
    float4 a0 = p0[0], a1 = p0[4], a2 = p0[8];
    float4 c0 = make_float4(0.f,0.f,0.f,0.f), c1 = c0, c2 = c0;
    if (live1) { c0 = p1[0]; c1 = p1[4]; c2 = p1[8]; }

    // --- stats for both rows ---
    float mu0, rs0, mu1, rs1;
    row_stats(a0, a1, a2, mu0, rs0);
    row_stats(c0, c1, c2, mu1, rs1);

    float4* q0 = dst + (size_t)r0 * 12 + lane4;
    float4* q1 = dst + (size_t)r1 * 12 + lane4;

    if (is_pair) {
        int i0, j0, i1, j1;
        if (lshift >= 0) {
            i0 = r0 >> lshift; j0 = r0 & (L - 1);
            i1 = r1 >> lshift; j1 = r1 & (L - 1);
        } else {
            i0 = r0 / L; j0 = r0 - i0 * L;
            i1 = r1 / L; j1 = r1 - i1 * L;
        }
        const float dx0 = x[3*i0]   - x[3*j0];
        const float dy0 = x[3*i0+1] - x[3*j0+1];
        const float dz0 = x[3*i0+2] - x[3*j0+2];
        const float dx1 = x[3*i1]   - x[3*j1];
        const float dy1 = x[3*i1+1] - x[3*j1+1];
        const float dz1 = x[3*i1+2] - x[3*j1+2];
        const int k0 = bin_of(sqrtf(dx0*dx0 + dy0*dy0 + dz0*dz0 + 1e-12f));
        const int k1 = bin_of(sqrtf(dx1*dx1 + dy1*dy1 + dz1*dz1 + 1e-12f));
        const float4* wr0 = sWb + k0 * 12 + lane4;
        const float4* wr1 = sWb + k1 * 12 + lane4;

        #pragma unroll
        for (int c = 0; c < 3; c++) {
            const float4 G = g4 [lane4 + 4 * c];
            const float4 B = be4[lane4 + 4 * c];
            {
                const float4 v = (c == 0) ? a0 : (c == 1) ? a1 : a2;
                const float4 w = wr0[4 * c];
                float4 o;
                o.x = fmaf((v.x - mu0) * rs0, G.x, B.x + w.x);
                o.y = fmaf((v.y - mu0) * rs0, G.y, B.y + w.y);
                o.z = fmaf((v.z - mu0) * rs0, G.z, B.z + w.z);
                o.w = fmaf((v.w - mu0) * rs0, G.w, B.w + w.w);
                q0[4 * c] = o;
            }
            if (live1) {
                const float4 v = (c == 0) ? c0 : (c == 1) ? c1 : c2;
                const float4 w = wr1[4 * c];
                float4 o;
                o.x = fmaf((v.x - mu1) * rs1, G.x, B.x + w.x);
                o.y = fmaf((v.y - mu1) * rs1, G.y, B.y + w.y);
                o.z = fmaf((v.z - mu1) * rs1, G.z, B.z + w.z);
                o.w = fmaf((v.w - mu1) * rs1, G.w, B.w + w.w);
                q1[4 * c] = o;
            }
        }
    } else {
        #pragma unroll
        for (int c = 0; c < 3; c++) {
            const float4 G = g4 [lane4 + 4 * c];
            const float4 B = be4[lane4 + 4 * c];
            {
                const float4 v = (c == 0) ? a0 : (c == 1) ? a1 : a2;
                float4 o;
                o.x = fmaf((v.x - mu0) * rs0, G.x, B.x);
                o.y = fmaf((v.y - mu0) * rs0, G.y, B.y);
                o.z = fmaf((v.z - mu0) * rs0, G.z, B.z);
                o.w = fmaf((v.w - mu0) * rs0, G.w, B.w);
                q0[4 * c] = o;
            }
            if (live1) {
                const float4 v = (c == 0) ? c0 : (c == 1) ? c1 : c2;
                float4 o;
                o.x = fmaf((v.x - mu1) * rs1, G.x, B.x);
                o.y = fmaf((v.y - mu1) * rs1, G.y, B.y);
                o.z = fmaf((v.z - mu1) * rs1, G.z, B.z);
                o.w = fmaf((v.w - mu1) * rs1, G.w, B.w);
                q1[4 * c] = o;
            }
        }
    }
}

// ---------------------------------------------------------------------------
extern "C" void kernel_launch(void* const* d_in, const int* in_sizes, int n_in,
                              void* d_out, int out_size) {
    const float* x      = (const float*)d_in[0];
    const float* single = (const float*)d_in[1];
    const float* pair   = (const float*)d_in[2];
    const float* W      = (const float*)d_in[3];
    const float* b      = (const float*)d_in[4];
    const float* gp     = (const float*)d_in[5];
    const float* bp     = (const float*)d_in[6];
    const float* gm     = (const float*)d_in[7];
    const float* bm     = (const float*)d_in[8];

    const int L = in_sizes[1] / DIM;            // single is [1, L, DIM]
    const int total = L * L;

    float* out        = (float*)d_out;
    float* single_out = out;                     // (single_out, pair_out) concatenated
    float* pair_out   = out + (size_t)L * DIM;

    int lshift = -1;
    if ((L & (L - 1)) == 0) {
        lshift = 0;
        while ((1 << lshift) < L) lshift++;
    }

    // 128 rows per block (256 threads, 4 per row, 2 rows per thread)
    const int blocksP = (total + 127) / 128;
    const int blocksS = (L + 127) / 128;

    fused_kernel<<<blocksP + blocksS, 256>>>(
        x,
        (const float4*)pair, (const float4*)single,
        (const float4*)W, (const float4*)b,
        (const float4*)gp, (const float4*)bp,
        (const float4*)gm, (const float4*)bm,
        (float4*)pair_out, (float4*)single_out,
        L, total, blocksP, lshift);
}